// round 7
// baseline (speedup 1.0000x reference)
#include <cuda_runtime.h>

// ---------------------------------------------------------------------------
// GAT (2-layer GATConv), N=50000, E=850000 (incl self-loops), F=128, H=4, D=32
// 8 launches:
//   1 k_init   2 k_hist   3 k_offsets (segment reservation, no full scan)
//   4 k_gemm L1 (pipelined f32x2 GEMM + fused el/er)   <- ncu capture slot
//   5 k_scatter (CSR bucket by dst)
//   6 k_gather L1 (fused edge softmax + weighted gather, warp/node)
//   7 k_gemm L2   8 k_gather L2
// ---------------------------------------------------------------------------

#define FULL 0xffffffffu
typedef unsigned long long ull;

constexpr int NN = 50000;
constexpr int EE = 850000;
constexpr int FH = 128;   // H*D
constexpr int HH = 4;

// scratch (device globals; no allocation allowed)
__device__ float g_feat[NN * FH];
__device__ float g_hid[NN * FH];
__device__ float g_el[NN * HH];
__device__ float g_er[NN * HH];
__device__ int   g_counts[NN];
__device__ int   g_cursor[NN];
__device__ int   g_off[NN];
__device__ int   g_total;
__device__ int   g_ssrc[EE];

// ---------------------------------------------------------------------------
__device__ __forceinline__ ull pack2(float lo, float hi) {
    ull r; asm("mov.b64 %0, {%1,%2};" : "=l"(r) : "f"(lo), "f"(hi)); return r;
}
__device__ __forceinline__ float2 unpack2(ull v) {
    float2 r; asm("mov.b64 {%0,%1}, %2;" : "=f"(r.x), "=f"(r.y) : "l"(v)); return r;
}
__device__ __forceinline__ void ffma2(ull& d, ull a, ull b) {
    asm("fma.rn.f32x2 %0, %1, %2, %0;" : "+l"(d) : "l"(a), "l"(b));
}
__device__ __forceinline__ float lk(float x, float s) { return x > 0.f ? x : x * s; }
__device__ __forceinline__ unsigned s2u(const void* p) {
    unsigned a;
    asm("{ .reg .u64 t; cvta.to.shared.u64 t, %1; cvt.u32.u64 %0, t; }"
        : "=r"(a) : "l"(p));
    return a;
}
#define CPA16(d, s) asm volatile("cp.async.ca.shared.global [%0], [%1], 16;" :: "r"(d), "l"(s))
#define CPA_COMMIT() asm volatile("cp.async.commit_group;")
#define CPA_WAIT0()  asm volatile("cp.async.wait_group 0;")

// ---------------------------------------------------------------------------
__global__ void k_init() {
    int i = blockIdx.x * blockDim.x + threadIdx.x;
    if (i < NN) { g_counts[i] = 0; g_cursor[i] = 0; }
    if (i == 0) g_total = 0;
}

__global__ void k_hist(const int* __restrict__ dst) {
    int i = blockIdx.x * blockDim.x + threadIdx.x;
    if (i < EE) atomicAdd(&g_counts[dst[i]], 1);
}

// Reserve a contiguous segment per node (segments need not be node-ordered):
// block exclusive scan + one atomicAdd on g_total per block.
__global__ void k_offsets() {
    __shared__ int wsum[32];
    __shared__ int sbase;
    int i = blockIdx.x * 1024 + threadIdx.x;
    int lane = threadIdx.x & 31, warp = threadIdx.x >> 5;
    int v = (i < NN) ? g_counts[i] : 0;

    int incl = v;
#pragma unroll
    for (int o = 1; o < 32; o <<= 1) {
        int t = __shfl_up_sync(FULL, incl, o);
        if (lane >= o) incl += t;
    }
    if (lane == 31) wsum[warp] = incl;
    __syncthreads();
    if (warp == 0) {
        int w = wsum[lane];
#pragma unroll
        for (int o = 1; o < 32; o <<= 1) {
            int t = __shfl_up_sync(FULL, w, o);
            if (lane >= o) w += t;
        }
        wsum[lane] = w;
        if (lane == 31) sbase = atomicAdd(&g_total, w);
    }
    __syncthreads();
    int excl = incl - v + (warp ? wsum[warp - 1] : 0);
    if (i < NN) g_off[i] = sbase + excl;
}

__global__ void k_scatter(const int* __restrict__ src, const int* __restrict__ dst) {
    int i = blockIdx.x * blockDim.x + threadIdx.x;
    if (i < EE) {
        int v = dst[i];
        int pos = g_off[v] + atomicAdd(&g_cursor[v], 1);
        g_ssrc[pos] = src[i];
    }
}

// ---------------------------------------------------------------------------
// Pipelined GEMM: feat[N,128] = X[N,128] @ W[128,128], packed fma.rn.f32x2.
// 128 threads / 4 warps, 64 rows/block (782 blocks, 4 CTAs/SM).
// Warp: 16 rows (8 row-pairs) x 128 cols (4 cols/lane).
//   - W chunks (KC=32): cp.async, double-buffered in smem.
//   - X chunks: LDG into regs during previous chunk's compute, then STS
//     transposed into paired-k layout Xsh2[rowpair][k] (ull = rows 2rp,2rp+1).
// Fused el/er attention-projection epilogue.
// ---------------------------------------------------------------------------
__global__ void __launch_bounds__(128) k_gemm(
        const float* __restrict__ X, const float* __restrict__ W,
        const float* __restrict__ al, const float* __restrict__ ar) {
    constexpr int GR = 64, KC = 32, NCH = FH / KC;   // 4 chunks
    __shared__ float Wsh[2][KC][FH];                 // 2 x 16KB
    __shared__ ull   Xsh2[GR / 2][KC];               // 8KB, [rowpair][k]

    int tid = threadIdx.x, lane = tid & 31, warp = tid >> 5;
    int row0 = blockIdx.x * GR;

    ull acc[8][4];
#pragma unroll
    for (int rp = 0; rp < 8; rp++)
#pragma unroll
        for (int c = 0; c < 4; c++) acc[rp][c] = 0ull;

    const float4* X4 = reinterpret_cast<const float4*>(X);

    // X loader mapping: thread handles rows r = (tid>>3) + 16*m (m=0..3),
    // float4 c = tid&7 (k-offset 4c..4c+3 within chunk)
    int xl_r = tid >> 3, xl_c = tid & 7;
    float4 xreg[4];

    // W loader mapping: chunk = 16KB = 1024 x 16B; thread copies units tid+128*j
    auto load_w = [&](int ch, int buf) {
        const char* gw = reinterpret_cast<const char*>(W) + ch * (KC * FH * 4);
        unsigned sw = s2u(&Wsh[buf][0][0]);
#pragma unroll
        for (int j = 0; j < 8; j++) {
            int u = tid + 128 * j;
            CPA16(sw + u * 16, gw + u * 16);
        }
        CPA_COMMIT();
    };
    auto load_x = [&](int ch) {
#pragma unroll
        for (int m = 0; m < 4; m++) {
            int r = xl_r + 16 * m;
            int row = row0 + r;
            xreg[m] = (row < NN) ? X4[row * 32 + ch * (KC / 4) + xl_c]
                                 : make_float4(0.f, 0.f, 0.f, 0.f);
        }
    };
    auto sts_x = [&]() {
        float* xf = reinterpret_cast<float*>(&Xsh2[0][0]);
#pragma unroll
        for (int m = 0; m < 4; m++) {
            int r = xl_r + 16 * m;
            int rp = r >> 1, par = r & 1;
            int base = (rp * KC + xl_c * 4) * 2 + par;
            xf[base + 0] = xreg[m].x;
            xf[base + 2] = xreg[m].y;
            xf[base + 4] = xreg[m].z;
            xf[base + 6] = xreg[m].w;
        }
    };

    // prologue: chunk 0
    load_w(0, 0);
    load_x(0);
    CPA_WAIT0();
    sts_x();
    __syncthreads();

    for (int ch = 0; ch < NCH; ch++) {
        int buf = ch & 1;
        if (ch + 1 < NCH) {
            load_w(ch + 1, buf ^ 1);
            load_x(ch + 1);
        }

#pragma unroll
        for (int k = 0; k < KC; k += 2) {
            float4 wA = *reinterpret_cast<const float4*>(&Wsh[buf][k][lane * 4]);
            float4 wB = *reinterpret_cast<const float4*>(&Wsh[buf][k + 1][lane * 4]);
            ull wA0 = pack2(wA.x, wA.x), wA1 = pack2(wA.y, wA.y);
            ull wA2 = pack2(wA.z, wA.z), wA3 = pack2(wA.w, wA.w);
            ull wB0 = pack2(wB.x, wB.x), wB1 = pack2(wB.y, wB.y);
            ull wB2 = pack2(wB.z, wB.z), wB3 = pack2(wB.w, wB.w);
#pragma unroll
            for (int rp = 0; rp < 8; rp++) {
                ulonglong2 a = *reinterpret_cast<const ulonglong2*>(
                    &Xsh2[warp * 8 + rp][k]);
                ffma2(acc[rp][0], a.x, wA0);
                ffma2(acc[rp][1], a.x, wA1);
                ffma2(acc[rp][2], a.x, wA2);
                ffma2(acc[rp][3], a.x, wA3);
                ffma2(acc[rp][0], a.y, wB0);
                ffma2(acc[rp][1], a.y, wB1);
                ffma2(acc[rp][2], a.y, wB2);
                ffma2(acc[rp][3], a.y, wB3);
            }
        }

        if (ch + 1 < NCH) {
            CPA_WAIT0();
            __syncthreads();      // compute done + next W in smem
            sts_x();
            __syncthreads();      // next X visible
        }
    }

    // epilogue: store feat + fused el/er (8-lane segmented reduction per head)
    int h = lane >> 3;
    float4 alv = reinterpret_cast<const float4*>(al)[h * 8 + (lane & 7)];
    float4 arv = reinterpret_cast<const float4*>(ar)[h * 8 + (lane & 7)];
    float4* feat4 = reinterpret_cast<float4*>(g_feat);

#pragma unroll
    for (int rp = 0; rp < 8; rp++) {
        float2 c0 = unpack2(acc[rp][0]), c1 = unpack2(acc[rp][1]);
        float2 c2 = unpack2(acc[rp][2]), c3 = unpack2(acc[rp][3]);
        int rlo = row0 + warp * 16 + rp * 2;
        int rhi = rlo + 1;
        if (rlo < NN) feat4[rlo * 32 + lane] = make_float4(c0.x, c1.x, c2.x, c3.x);
        if (rhi < NN) feat4[rhi * 32 + lane] = make_float4(c0.y, c1.y, c2.y, c3.y);

        float el_lo = c0.x * alv.x + c1.x * alv.y + c2.x * alv.z + c3.x * alv.w;
        float er_lo = c0.x * arv.x + c1.x * arv.y + c2.x * arv.z + c3.x * arv.w;
        float el_hi = c0.y * alv.x + c1.y * alv.y + c2.y * alv.z + c3.y * alv.w;
        float er_hi = c0.y * arv.x + c1.y * arv.y + c2.y * arv.z + c3.y * arv.w;
#pragma unroll
        for (int o = 4; o; o >>= 1) {
            el_lo += __shfl_xor_sync(FULL, el_lo, o);
            er_lo += __shfl_xor_sync(FULL, er_lo, o);
            el_hi += __shfl_xor_sync(FULL, el_hi, o);
            er_hi += __shfl_xor_sync(FULL, er_hi, o);
        }
        if ((lane & 7) == 0) {
            if (rlo < NN) { g_el[rlo * HH + h] = el_lo; g_er[rlo * HH + h] = er_lo; }
            if (rhi < NN) { g_el[rhi * HH + h] = el_hi; g_er[rhi * HH + h] = er_hi; }
        }
    }
}

// ---------------------------------------------------------------------------
// Fused softmax + gather: one warp per dst node (no max pass; scores are O(1),
// softmax shift-invariant). Pass A: per-head denominators. Pass B: recompute
// exp, weighted float4 gather of feat[src] in registers.
// ---------------------------------------------------------------------------
__device__ __forceinline__ float4 wred_sum4(float4 v) {
#pragma unroll
    for (int o = 16; o; o >>= 1) {
        v.x += __shfl_xor_sync(FULL, v.x, o);
        v.y += __shfl_xor_sync(FULL, v.y, o);
        v.z += __shfl_xor_sync(FULL, v.z, o);
        v.w += __shfl_xor_sync(FULL, v.w, o);
    }
    return v;
}

__global__ void k_gather(const float* __restrict__ bias, float* __restrict__ out,
                         float act_slope, int apply_act) {
    int wg = (blockIdx.x * blockDim.x + threadIdx.x) >> 5;
    int lane = threadIdx.x & 31;
    if (wg >= NN) return;
    int v = wg;
    int start = g_off[v];
    int end = start + g_counts[v];

    const float4* feat4 = reinterpret_cast<const float4*>(g_feat);
    const float4* el4 = reinterpret_cast<const float4*>(g_el);
    const float* elf = g_el;

    float4 erv = reinterpret_cast<const float4*>(g_er)[v];

    float4 sm = make_float4(0.f, 0.f, 0.f, 0.f);
    for (int p = start + lane; p < end; p += 32) {
        int s = g_ssrc[p];
        float4 e = el4[s];
        sm.x += __expf(lk(e.x + erv.x, 0.2f));
        sm.y += __expf(lk(e.y + erv.y, 0.2f));
        sm.z += __expf(lk(e.z + erv.z, 0.2f));
        sm.w += __expf(lk(e.w + erv.w, 0.2f));
    }
    sm = wred_sum4(sm);

    int h = lane >> 3;
    float shd = (h == 0) ? sm.x : (h == 1) ? sm.y : (h == 2) ? sm.z : sm.w;
    float erh = (h == 0) ? erv.x : (h == 1) ? erv.y : (h == 2) ? erv.z : erv.w;
    float inv = 1.f / shd;

    float4 a0 = make_float4(0, 0, 0, 0), a1 = a0, a2 = a0, a3 = a0;
    int p = start;
#define STEP(PP, ACC)                                            \
    {                                                            \
        int s_ = g_ssrc[PP];                                     \
        float a_ = __expf(lk(elf[s_ * 4 + h] + erh, 0.2f)) * inv;\
        float4 f_ = feat4[s_ * 32 + lane];                       \
        ACC.x = fmaf(a_, f_.x, ACC.x);                           \
        ACC.y = fmaf(a_, f_.y, ACC.y);                           \
        ACC.z = fmaf(a_, f_.z, ACC.z);                           \
        ACC.w = fmaf(a_, f_.w, ACC.w);                           \
    }
    for (; p + 4 <= end; p += 4) {
        STEP(p + 0, a0); STEP(p + 1, a1); STEP(p + 2, a2); STEP(p + 3, a3);
    }
    for (; p < end; ++p) STEP(p, a0);
#undef STEP
    float4 acc;
    acc.x = (a0.x + a1.x) + (a2.x + a3.x);
    acc.y = (a0.y + a1.y) + (a2.y + a3.y);
    acc.z = (a0.z + a1.z) + (a2.z + a3.z);
    acc.w = (a0.w + a1.w) + (a2.w + a3.w);

    float4 b = reinterpret_cast<const float4*>(bias)[lane];
    acc.x += b.x; acc.y += b.y; acc.z += b.z; acc.w += b.w;
    if (apply_act) {
        acc.x = lk(acc.x, act_slope);
        acc.y = lk(acc.y, act_slope);
        acc.z = lk(acc.z, act_slope);
        acc.w = lk(acc.w, act_slope);
    }
    reinterpret_cast<float4*>(out)[v * 32 + lane] = acc;
}

// ---------------------------------------------------------------------------
extern "C" void kernel_launch(void* const* d_in, const int* in_sizes, int n_in,
                              void* d_out, int out_size) {
    const float* x   = (const float*)d_in[0];
    const int*   src = (const int*)d_in[1];
    const int*   dst = (const int*)d_in[2];
    const float* W1  = (const float*)d_in[3];
    const float* al1 = (const float*)d_in[4];
    const float* ar1 = (const float*)d_in[5];
    const float* b1  = (const float*)d_in[6];
    const float* W2  = (const float*)d_in[7];
    const float* al2 = (const float*)d_in[8];
    const float* ar2 = (const float*)d_in[9];
    const float* b2  = (const float*)d_in[10];
    float* out = (float*)d_out;

    void* p_hid = nullptr;
    cudaGetSymbolAddress(&p_hid, g_hid);
    float* hid = (float*)p_hid;

    int eblocks = (EE + 255) / 256;
    int nblocks = (NN + 255) / 256;
    int gemm_blocks = (NN + 63) / 64;        // 782
    int gather_blocks = (NN + 7) / 8;        // 8 warps/block
    int off_blocks = (NN + 1023) / 1024;     // 49

    k_init<<<nblocks, 256>>>();                            // 1
    k_hist<<<eblocks, 256>>>(dst);                         // 2
    k_offsets<<<off_blocks, 1024>>>();                     // 3
    k_gemm<<<gemm_blocks, 128>>>(x, W1, al1, ar1);         // 4 <- ncu capture
    k_scatter<<<eblocks, 256>>>(src, dst);                 // 5
    k_gather<<<gather_blocks, 256>>>(b1, hid, 0.01f, 1);   // 6
    k_gemm<<<gemm_blocks, 128>>>(hid, W2, al2, ar2);       // 7
    k_gather<<<gather_blocks, 256>>>(b2, out, 0.0f, 0);    // 8
}

// round 9
// speedup vs baseline: 1.0062x; 1.0062x over previous
#include <cuda_runtime.h>

// ---------------------------------------------------------------------------
// GAT (2-layer GATConv), N=50000, E=850000 (incl self-loops), F=128, H=4, D=32
// 8 launches:
//   1 k_init   2 k_hist   3 k_offsets (segment reservation, no full scan)
//   4 k_gemm L1 (pipelined f32x2 GEMM + fused el/er)   <- ncu capture slot
//   5 k_scatter (CSR bucket by dst)
//   6 k_gather L1 (fused edge softmax + weighted gather, warp/node)
//   7 k_gemm L2   8 k_gather L2
// ---------------------------------------------------------------------------

#define FULL 0xffffffffu
typedef unsigned long long ull;

constexpr int NN = 50000;
constexpr int EE = 850000;
constexpr int FH = 128;   // H*D
constexpr int HH = 4;

// scratch (device globals; no allocation allowed)
__device__ float g_feat[NN * FH];
__device__ float g_hid[NN * FH];
__device__ float g_el[NN * HH];
__device__ float g_er[NN * HH];
__device__ int   g_counts[NN];
__device__ int   g_cursor[NN];
__device__ int   g_off[NN];
__device__ int   g_total;
__device__ int   g_ssrc[EE];

// ---------------------------------------------------------------------------
__device__ __forceinline__ ull pack2(float lo, float hi) {
    ull r; asm("mov.b64 %0, {%1,%2};" : "=l"(r) : "f"(lo), "f"(hi)); return r;
}
__device__ __forceinline__ float2 unpack2(ull v) {
    float2 r; asm("mov.b64 {%0,%1}, %2;" : "=f"(r.x), "=f"(r.y) : "l"(v)); return r;
}
__device__ __forceinline__ void ffma2(ull& d, ull a, ull b) {
    asm("fma.rn.f32x2 %0, %1, %2, %0;" : "+l"(d) : "l"(a), "l"(b));
}
__device__ __forceinline__ float lk(float x, float s) { return x > 0.f ? x : x * s; }
__device__ __forceinline__ unsigned s2u(const void* p) {
    unsigned a;
    asm("{ .reg .u64 t; cvta.to.shared.u64 t, %1; cvt.u32.u64 %0, t; }"
        : "=r"(a) : "l"(p));
    return a;
}
#define CPA16(d, s) asm volatile("cp.async.ca.shared.global [%0], [%1], 16;" :: "r"(d), "l"(s))
#define CPA_COMMIT() asm volatile("cp.async.commit_group;")
#define CPA_WAIT0()  asm volatile("cp.async.wait_group 0;")

// ---------------------------------------------------------------------------
__global__ void k_init() {
    int i = blockIdx.x * blockDim.x + threadIdx.x;
    if (i < NN) { g_counts[i] = 0; g_cursor[i] = 0; }
    if (i == 0) g_total = 0;
}

__global__ void k_hist(const int* __restrict__ dst) {
    int i = blockIdx.x * blockDim.x + threadIdx.x;
    if (i < EE) atomicAdd(&g_counts[dst[i]], 1);
}

// Reserve a contiguous segment per node (segments need not be node-ordered):
// block exclusive scan + one atomicAdd on g_total per block.
__global__ void k_offsets() {
    __shared__ int wsum[32];
    __shared__ int sbase;
    int i = blockIdx.x * 1024 + threadIdx.x;
    int lane = threadIdx.x & 31, warp = threadIdx.x >> 5;
    int v = (i < NN) ? g_counts[i] : 0;

    int incl = v;
#pragma unroll
    for (int o = 1; o < 32; o <<= 1) {
        int t = __shfl_up_sync(FULL, incl, o);
        if (lane >= o) incl += t;
    }
    if (lane == 31) wsum[warp] = incl;
    __syncthreads();
    if (warp == 0) {
        int w = wsum[lane];
#pragma unroll
        for (int o = 1; o < 32; o <<= 1) {
            int t = __shfl_up_sync(FULL, w, o);
            if (lane >= o) w += t;
        }
        wsum[lane] = w;
        if (lane == 31) sbase = atomicAdd(&g_total, w);
    }
    __syncthreads();
    int excl = incl - v + (warp ? wsum[warp - 1] : 0);
    if (i < NN) g_off[i] = sbase + excl;
}

__global__ void k_scatter(const int* __restrict__ src, const int* __restrict__ dst) {
    int i = blockIdx.x * blockDim.x + threadIdx.x;
    if (i < EE) {
        int v = dst[i];
        int pos = g_off[v] + atomicAdd(&g_cursor[v], 1);
        g_ssrc[pos] = src[i];
    }
}

// ---------------------------------------------------------------------------
// Pipelined GEMM: feat[N,128] = X[N,128] @ W[128,128], packed fma.rn.f32x2.
// 256 threads / 8 warps, 128 rows/block (391 blocks, 2 CTAs/SM).
// Warp: 16 rows (8 row-pairs) x 128 cols (4 cols/lane).
//   - W chunks (KC=32): cp.async, double-buffered in smem.
//   - X chunks: LDG to regs during previous chunk's compute, then STS into
//     paired-k layout (ull = rows 2rp,2rp+1 at k), row pitch 68 floats to
//     spread STS banks. Inner loop reads ulonglong2 (k,k+1 pair) broadcasts.
// __launch_bounds__(256,2) pins regs <=128 so 2 CTAs/SM survive.
// Fused el/er attention-projection epilogue.
// ---------------------------------------------------------------------------
__global__ void __launch_bounds__(256, 2) k_gemm(
        const float* __restrict__ X, const float* __restrict__ W,
        const float* __restrict__ al, const float* __restrict__ ar) {
    constexpr int GR = 128, KC = 32, NCH = FH / KC;   // 4 chunks
    constexpr int XPITCH = 2 * KC + 4;                // 68 floats per row-pair
    __shared__ float Wsh[2][KC][FH];                  // 2 x 16KB
    __shared__ float Xsh[(GR / 2) * XPITCH];          // 17KB paired-k

    int tid = threadIdx.x, lane = tid & 31, warp = tid >> 5;
    int row0 = blockIdx.x * GR;

    ull acc[8][4];
#pragma unroll
    for (int rp = 0; rp < 8; rp++)
#pragma unroll
        for (int c = 0; c < 4; c++) acc[rp][c] = 0ull;

    const float4* X4 = reinterpret_cast<const float4*>(X);

    // X loader: thread handles rows r = (tid>>3) + 32*m (m=0..3), float4 c=tid&7
    int xl_r = tid >> 3, xl_c = tid & 7;
    float4 xreg[4];

    auto load_w = [&](int ch, int buf) {
        const char* gw = reinterpret_cast<const char*>(W) + ch * (KC * FH * 4);
        unsigned sw = s2u(&Wsh[buf][0][0]);
#pragma unroll
        for (int j = 0; j < 4; j++) {
            int u = tid + 256 * j;
            CPA16(sw + u * 16, gw + u * 16);
        }
        CPA_COMMIT();
    };
    auto load_x = [&](int ch) {
#pragma unroll
        for (int m = 0; m < 4; m++) {
            int row = row0 + xl_r + 32 * m;
            xreg[m] = (row < NN) ? X4[row * 32 + ch * (KC / 4) + xl_c]
                                 : make_float4(0.f, 0.f, 0.f, 0.f);
        }
    };
    auto sts_x = [&]() {
#pragma unroll
        for (int m = 0; m < 4; m++) {
            int r = xl_r + 32 * m;
            int rp = r >> 1, par = r & 1;
            int base = rp * XPITCH + xl_c * 8 + par;   // k = 4c+j -> +2j
            Xsh[base + 0] = xreg[m].x;
            Xsh[base + 2] = xreg[m].y;
            Xsh[base + 4] = xreg[m].z;
            Xsh[base + 6] = xreg[m].w;
        }
    };

    // prologue: chunk 0
    load_w(0, 0);
    load_x(0);
    CPA_WAIT0();
    sts_x();
    __syncthreads();

    for (int ch = 0; ch < NCH; ch++) {
        int buf = ch & 1;
        if (ch + 1 < NCH) {
            load_w(ch + 1, buf ^ 1);
            load_x(ch + 1);
        }

#pragma unroll
        for (int k = 0; k < KC; k += 2) {
            float4 wA = *reinterpret_cast<const float4*>(&Wsh[buf][k][lane * 4]);
            float4 wB = *reinterpret_cast<const float4*>(&Wsh[buf][k + 1][lane * 4]);
            ull wA0 = pack2(wA.x, wA.x), wA1 = pack2(wA.y, wA.y);
            ull wA2 = pack2(wA.z, wA.z), wA3 = pack2(wA.w, wA.w);
            ull wB0 = pack2(wB.x, wB.x), wB1 = pack2(wB.y, wB.y);
            ull wB2 = pack2(wB.z, wB.z), wB3 = pack2(wB.w, wB.w);
#pragma unroll
            for (int rp = 0; rp < 8; rp++) {
                ulonglong2 a = *reinterpret_cast<const ulonglong2*>(
                    &Xsh[(warp * 8 + rp) * XPITCH + 2 * k]);
                ffma2(acc[rp][0], a.x, wA0);
                ffma2(acc[rp][1], a.x, wA1);
                ffma2(acc[rp][2], a.x, wA2);
                ffma2(acc[rp][3], a.x, wA3);
                ffma2(acc[rp][0], a.y, wB0);
                ffma2(acc[rp][1], a.y, wB1);
                ffma2(acc[rp][2], a.y, wB2);
                ffma2(acc[rp][3], a.y, wB3);
            }
        }

        if (ch + 1 < NCH) {
            CPA_WAIT0();
            __syncthreads();      // compute done + next W landed
            sts_x();
            __syncthreads();      // next X visible
        }
    }

    // epilogue: store feat + fused el/er (8-lane segmented reduction per head)
    int h = lane >> 3;
    float4 alv = reinterpret_cast<const float4*>(al)[h * 8 + (lane & 7)];
    float4 arv = reinterpret_cast<const float4*>(ar)[h * 8 + (lane & 7)];
    float4* feat4 = reinterpret_cast<float4*>(g_feat);

#pragma unroll
    for (int rp = 0; rp < 8; rp++) {
        float2 c0 = unpack2(acc[rp][0]), c1 = unpack2(acc[rp][1]);
        float2 c2 = unpack2(acc[rp][2]), c3 = unpack2(acc[rp][3]);
        int rlo = row0 + warp * 16 + rp * 2;
        int rhi = rlo + 1;
        if (rlo < NN) feat4[rlo * 32 + lane] = make_float4(c0.x, c1.x, c2.x, c3.x);
        if (rhi < NN) feat4[rhi * 32 + lane] = make_float4(c0.y, c1.y, c2.y, c3.y);

        float el_lo = c0.x * alv.x + c1.x * alv.y + c2.x * alv.z + c3.x * alv.w;
        float er_lo = c0.x * arv.x + c1.x * arv.y + c2.x * arv.z + c3.x * arv.w;
        float el_hi = c0.y * alv.x + c1.y * alv.y + c2.y * alv.z + c3.y * alv.w;
        float er_hi = c0.y * arv.x + c1.y * arv.y + c2.y * arv.z + c3.y * arv.w;
#pragma unroll
        for (int o = 4; o; o >>= 1) {
            el_lo += __shfl_xor_sync(FULL, el_lo, o);
            er_lo += __shfl_xor_sync(FULL, er_lo, o);
            el_hi += __shfl_xor_sync(FULL, el_hi, o);
            er_hi += __shfl_xor_sync(FULL, er_hi, o);
        }
        if ((lane & 7) == 0) {
            if (rlo < NN) { g_el[rlo * HH + h] = el_lo; g_er[rlo * HH + h] = er_lo; }
            if (rhi < NN) { g_el[rhi * HH + h] = el_hi; g_er[rhi * HH + h] = er_hi; }
        }
    }
}

// ---------------------------------------------------------------------------
// Fused softmax + gather: one warp per dst node (no max pass; scores are O(1),
// softmax shift-invariant). Pass A: per-head denominators. Pass B: recompute
// exp, weighted float4 gather of feat[src] in registers.
// ---------------------------------------------------------------------------
__device__ __forceinline__ float4 wred_sum4(float4 v) {
#pragma unroll
    for (int o = 16; o; o >>= 1) {
        v.x += __shfl_xor_sync(FULL, v.x, o);
        v.y += __shfl_xor_sync(FULL, v.y, o);
        v.z += __shfl_xor_sync(FULL, v.z, o);
        v.w += __shfl_xor_sync(FULL, v.w, o);
    }
    return v;
}

__global__ void k_gather(const float* __restrict__ bias, float* __restrict__ out,
                         float act_slope, int apply_act) {
    int wg = (blockIdx.x * blockDim.x + threadIdx.x) >> 5;
    int lane = threadIdx.x & 31;
    if (wg >= NN) return;
    int v = wg;
    int start = g_off[v];
    int end = start + g_counts[v];

    const float4* feat4 = reinterpret_cast<const float4*>(g_feat);
    const float4* el4 = reinterpret_cast<const float4*>(g_el);
    const float* elf = g_el;

    float4 erv = reinterpret_cast<const float4*>(g_er)[v];

    float4 sm = make_float4(0.f, 0.f, 0.f, 0.f);
    for (int p = start + lane; p < end; p += 32) {
        int s = g_ssrc[p];
        float4 e = el4[s];
        sm.x += __expf(lk(e.x + erv.x, 0.2f));
        sm.y += __expf(lk(e.y + erv.y, 0.2f));
        sm.z += __expf(lk(e.z + erv.z, 0.2f));
        sm.w += __expf(lk(e.w + erv.w, 0.2f));
    }
    sm = wred_sum4(sm);

    int h = lane >> 3;
    float shd = (h == 0) ? sm.x : (h == 1) ? sm.y : (h == 2) ? sm.z : sm.w;
    float erh = (h == 0) ? erv.x : (h == 1) ? erv.y : (h == 2) ? erv.z : erv.w;
    float inv = 1.f / shd;

    float4 a0 = make_float4(0, 0, 0, 0), a1 = a0, a2 = a0, a3 = a0;
    int p = start;
#define STEP(PP, ACC)                                            \
    {                                                            \
        int s_ = g_ssrc[PP];                                     \
        float a_ = __expf(lk(elf[s_ * 4 + h] + erh, 0.2f)) * inv;\
        float4 f_ = feat4[s_ * 32 + lane];                       \
        ACC.x = fmaf(a_, f_.x, ACC.x);                           \
        ACC.y = fmaf(a_, f_.y, ACC.y);                           \
        ACC.z = fmaf(a_, f_.z, ACC.z);                           \
        ACC.w = fmaf(a_, f_.w, ACC.w);                           \
    }
    for (; p + 4 <= end; p += 4) {
        STEP(p + 0, a0); STEP(p + 1, a1); STEP(p + 2, a2); STEP(p + 3, a3);
    }
    for (; p < end; ++p) STEP(p, a0);
#undef STEP
    float4 acc;
    acc.x = (a0.x + a1.x) + (a2.x + a3.x);
    acc.y = (a0.y + a1.y) + (a2.y + a3.y);
    acc.z = (a0.z + a1.z) + (a2.z + a3.z);
    acc.w = (a0.w + a1.w) + (a2.w + a3.w);

    float4 b = reinterpret_cast<const float4*>(bias)[lane];
    acc.x += b.x; acc.y += b.y; acc.z += b.z; acc.w += b.w;
    if (apply_act) {
        acc.x = lk(acc.x, act_slope);
        acc.y = lk(acc.y, act_slope);
        acc.z = lk(acc.z, act_slope);
        acc.w = lk(acc.w, act_slope);
    }
    reinterpret_cast<float4*>(out)[v * 32 + lane] = acc;
}

// ---------------------------------------------------------------------------
extern "C" void kernel_launch(void* const* d_in, const int* in_sizes, int n_in,
                              void* d_out, int out_size) {
    const float* x   = (const float*)d_in[0];
    const int*   src = (const int*)d_in[1];
    const int*   dst = (const int*)d_in[2];
    const float* W1  = (const float*)d_in[3];
    const float* al1 = (const float*)d_in[4];
    const float* ar1 = (const float*)d_in[5];
    const float* b1  = (const float*)d_in[6];
    const float* W2  = (const float*)d_in[7];
    const float* al2 = (const float*)d_in[8];
    const float* ar2 = (const float*)d_in[9];
    const float* b2  = (const float*)d_in[10];
    float* out = (float*)d_out;

    void* p_hid = nullptr;
    cudaGetSymbolAddress(&p_hid, g_hid);
    float* hid = (float*)p_hid;

    int eblocks = (EE + 255) / 256;
    int nblocks = (NN + 255) / 256;
    int gemm_blocks = (NN + 127) / 128;      // 391
    int gather_blocks = (NN + 7) / 8;        // 8 warps/block
    int off_blocks = (NN + 1023) / 1024;     // 49

    k_init<<<nblocks, 256>>>();                            // 1
    k_hist<<<eblocks, 256>>>(dst);                         // 2
    k_offsets<<<off_blocks, 1024>>>();                     // 3
    k_gemm<<<gemm_blocks, 256>>>(x, W1, al1, ar1);         // 4 <- ncu capture
    k_scatter<<<eblocks, 256>>>(src, dst);                 // 5
    k_gather<<<gather_blocks, 256>>>(b1, hid, 0.01f, 1);   // 6
    k_gemm<<<gemm_blocks, 256>>>(hid, W2, al2, ar2);       // 7
    k_gather<<<gather_blocks, 256>>>(b2, out, 0.0f, 0);    // 8
}

// round 10
// speedup vs baseline: 1.5093x; 1.5000x over previous
#include <cuda_runtime.h>

// ---------------------------------------------------------------------------
// GAT (2-layer GATConv), N=50000, E=850000 (incl self-loops), F=128, H=4, D=32
// 8 launches:
//   1 k_init   2 k_hist   3 k_offsets (segment reservation, no full scan)
//   4 k_gemm L1 (W-resident f32x2 GEMM + fused el/er)   <- ncu capture slot
//   5 k_scatter (CSR bucket by dst)
//   6 k_gather L1 (fused edge softmax + weighted gather, warp/node)
//   7 k_gemm L2   8 k_gather L2
// ---------------------------------------------------------------------------

#define FULL 0xffffffffu
typedef unsigned long long ull;

constexpr int NN = 50000;
constexpr int EE = 850000;
constexpr int FH = 128;   // H*D
constexpr int HH = 4;

// scratch (device globals; no allocation allowed)
__device__ float g_feat[NN * FH];
__device__ float g_hid[NN * FH];
__device__ float g_el[NN * HH];
__device__ float g_er[NN * HH];
__device__ int   g_counts[NN];
__device__ int   g_cursor[NN];
__device__ int   g_off[NN];
__device__ int   g_total;
__device__ int   g_ssrc[EE];

// ---------------------------------------------------------------------------
__device__ __forceinline__ ull pack2(float lo, float hi) {
    ull r; asm("mov.b64 %0, {%1,%2};" : "=l"(r) : "f"(lo), "f"(hi)); return r;
}
__device__ __forceinline__ float2 unpack2(ull v) {
    float2 r; asm("mov.b64 {%0,%1}, %2;" : "=f"(r.x), "=f"(r.y) : "l"(v)); return r;
}
__device__ __forceinline__ void ffma2(ull& d, ull a, ull b) {
    asm("fma.rn.f32x2 %0, %1, %2, %0;" : "+l"(d) : "l"(a), "l"(b));
}
__device__ __forceinline__ float lk(float x, float s) { return x > 0.f ? x : x * s; }
__device__ __forceinline__ unsigned s2u(const void* p) {
    unsigned a;
    asm("{ .reg .u64 t; cvta.to.shared.u64 t, %1; cvt.u32.u64 %0, t; }"
        : "=r"(a) : "l"(p));
    return a;
}
#define CPA16(d, s) asm volatile("cp.async.ca.shared.global [%0], [%1], 16;" :: "r"(d), "l"(s))
#define CPA_COMMIT() asm volatile("cp.async.commit_group;")
#define CPA_WAIT0()  asm volatile("cp.async.wait_group 0;")

// ---------------------------------------------------------------------------
__global__ void k_init() {
    int i = blockIdx.x * blockDim.x + threadIdx.x;
    if (i < NN) { g_counts[i] = 0; g_cursor[i] = 0; }
    if (i == 0) g_total = 0;
}

__global__ void k_hist(const int* __restrict__ dst) {
    int i = blockIdx.x * blockDim.x + threadIdx.x;
    if (i < EE) atomicAdd(&g_counts[dst[i]], 1);
}

// Reserve a contiguous segment per node (segments need not be node-ordered):
// block exclusive scan + one atomicAdd on g_total per block.
__global__ void k_offsets() {
    __shared__ int wsum[32];
    __shared__ int sbase;
    int i = blockIdx.x * 1024 + threadIdx.x;
    int lane = threadIdx.x & 31, warp = threadIdx.x >> 5;
    int v = (i < NN) ? g_counts[i] : 0;

    int incl = v;
#pragma unroll
    for (int o = 1; o < 32; o <<= 1) {
        int t = __shfl_up_sync(FULL, incl, o);
        if (lane >= o) incl += t;
    }
    if (lane == 31) wsum[warp] = incl;
    __syncthreads();
    if (warp == 0) {
        int w = wsum[lane];
#pragma unroll
        for (int o = 1; o < 32; o <<= 1) {
            int t = __shfl_up_sync(FULL, w, o);
            if (lane >= o) w += t;
        }
        wsum[lane] = w;
        if (lane == 31) sbase = atomicAdd(&g_total, w);
    }
    __syncthreads();
    int excl = incl - v + (warp ? wsum[warp - 1] : 0);
    if (i < NN) g_off[i] = sbase + excl;
}

__global__ void k_scatter(const int* __restrict__ src, const int* __restrict__ dst) {
    int i = blockIdx.x * blockDim.x + threadIdx.x;
    if (i < EE) {
        int v = dst[i];
        int pos = g_off[v] + atomicAdd(&g_cursor[v], 1);
        g_ssrc[pos] = src[i];
    }
}

// ---------------------------------------------------------------------------
// W-resident pipelined GEMM: feat[N,128] = X[N,128] @ W[128,128], fma.rn.f32x2.
// 256 threads / 8 warps, 128 rows/block (391 blocks, 2 CTAs/SM).
// Warp: 16 rows (8 row-pairs) x 128 cols (4 cols/lane). Same inner loop as the
// proven 104-reg version (scalar k-major X tile, LDS.64 row-pairs).
//   - W: FULL 64KB image cp.async'd ONCE per block into dynamic smem.
//   - X: double-buffered 32-k chunks; LDG for ch+1 issued before compute(ch);
//     STS lands after compute; ONE __syncthreads per chunk.
// Dynamic smem 96.5KB/block -> 2 CTAs/SM (193KB < 228KB).
// ---------------------------------------------------------------------------
__global__ void __launch_bounds__(256) k_gemm(
        const float* __restrict__ X, const float* __restrict__ W,
        const float* __restrict__ al, const float* __restrict__ ar) {
    constexpr int GR = 128, KC = 32, NCH = FH / KC;   // 4 chunks
    constexpr int XP = GR + 2;                        // 130: bank spread
    extern __shared__ float smem[];
    float* Wsh = smem;                                // [128][128] = 64KB
    float* Xsh = smem + FH * FH;                      // [2][KC][XP] = 33.3KB

    int tid = threadIdx.x, lane = tid & 31, warp = tid >> 5;
    int row0 = blockIdx.x * GR;

    ull acc[8][4];
#pragma unroll
    for (int rp = 0; rp < 8; rp++)
#pragma unroll
        for (int c = 0; c < 4; c++) acc[rp][c] = 0ull;

    const float4* X4 = reinterpret_cast<const float4*>(X);

    // W: one cp.async burst, 4096 x 16B units across 256 threads
    {
        const char* gw = reinterpret_cast<const char*>(W);
        unsigned sw = s2u(Wsh);
#pragma unroll
        for (int j = 0; j < 16; j++) {
            int u = tid + 256 * j;
            CPA16(sw + u * 16, gw + u * 16);
        }
        CPA_COMMIT();
    }

    // X loader mapping: float4 col c = tid&7, rows r = (tid>>3)+32m
    int xl_c = tid & 7, xl_rb = tid >> 3;
    float4 xreg[4];
    auto load_x = [&](int ch) {
#pragma unroll
        for (int m = 0; m < 4; m++) {
            int row = row0 + xl_rb + 32 * m;
            xreg[m] = (row < NN) ? X4[row * 32 + ch * (KC / 4) + xl_c]
                                 : make_float4(0.f, 0.f, 0.f, 0.f);
        }
    };
    auto sts_x = [&](int buf) {
        float* xb = Xsh + buf * (KC * XP);
#pragma unroll
        for (int m = 0; m < 4; m++) {
            int r = xl_rb + 32 * m;
            xb[(4 * xl_c + 0) * XP + r] = xreg[m].x;
            xb[(4 * xl_c + 1) * XP + r] = xreg[m].y;
            xb[(4 * xl_c + 2) * XP + r] = xreg[m].z;
            xb[(4 * xl_c + 3) * XP + r] = xreg[m].w;
        }
    };

    // prologue: X chunk 0 in buffer 0; wait W + X
    load_x(0);
    CPA_WAIT0();          // W landed
    sts_x(0);
    __syncthreads();

    for (int ch = 0; ch < NCH; ch++) {
        int buf = ch & 1;
        if (ch + 1 < NCH) load_x(ch + 1);   // LDG in flight during compute

        const float* xb = Xsh + buf * (KC * XP);
#pragma unroll 4
        for (int k = 0; k < KC; k++) {
            float4 w = *reinterpret_cast<const float4*>(
                &Wsh[(ch * KC + k) * FH + lane * 4]);
            ull w0 = pack2(w.x, w.x), w1 = pack2(w.y, w.y);
            ull w2 = pack2(w.z, w.z), w3 = pack2(w.w, w.w);
            const ull* arow = reinterpret_cast<const ull*>(&xb[k * XP + warp * 16]);
#pragma unroll
            for (int rp = 0; rp < 8; rp++) {
                ull a2 = arow[rp];
                ffma2(acc[rp][0], a2, w0);
                ffma2(acc[rp][1], a2, w1);
                ffma2(acc[rp][2], a2, w2);
                ffma2(acc[rp][3], a2, w3);
            }
        }

        if (ch + 1 < NCH) {
            sts_x(buf ^ 1);       // idle buffer; safe (readers of it synced out)
            __syncthreads();      // one barrier per chunk
        }
    }

    // epilogue: store feat + fused el/er (8-lane segmented reduction per head)
    int h = lane >> 3;
    float4 alv = reinterpret_cast<const float4*>(al)[h * 8 + (lane & 7)];
    float4 arv = reinterpret_cast<const float4*>(ar)[h * 8 + (lane & 7)];
    float4* feat4 = reinterpret_cast<float4*>(g_feat);

#pragma unroll
    for (int rp = 0; rp < 8; rp++) {
        float2 c0 = unpack2(acc[rp][0]), c1 = unpack2(acc[rp][1]);
        float2 c2 = unpack2(acc[rp][2]), c3 = unpack2(acc[rp][3]);
        int rlo = row0 + warp * 16 + rp * 2;
        int rhi = rlo + 1;
        if (rlo < NN) feat4[rlo * 32 + lane] = make_float4(c0.x, c1.x, c2.x, c3.x);
        if (rhi < NN) feat4[rhi * 32 + lane] = make_float4(c0.y, c1.y, c2.y, c3.y);

        float el_lo = c0.x * alv.x + c1.x * alv.y + c2.x * alv.z + c3.x * alv.w;
        float er_lo = c0.x * arv.x + c1.x * arv.y + c2.x * arv.z + c3.x * arv.w;
        float el_hi = c0.y * alv.x + c1.y * alv.y + c2.y * alv.z + c3.y * alv.w;
        float er_hi = c0.y * arv.x + c1.y * arv.y + c2.y * arv.z + c3.y * arv.w;
#pragma unroll
        for (int o = 4; o; o >>= 1) {
            el_lo += __shfl_xor_sync(FULL, el_lo, o);
            er_lo += __shfl_xor_sync(FULL, er_lo, o);
            el_hi += __shfl_xor_sync(FULL, el_hi, o);
            er_hi += __shfl_xor_sync(FULL, er_hi, o);
        }
        if ((lane & 7) == 0) {
            if (rlo < NN) { g_el[rlo * HH + h] = el_lo; g_er[rlo * HH + h] = er_lo; }
            if (rhi < NN) { g_el[rhi * HH + h] = el_hi; g_er[rhi * HH + h] = er_hi; }
        }
    }
}

// ---------------------------------------------------------------------------
// Fused softmax + gather: one warp per dst node (no max pass; scores are O(1),
// softmax shift-invariant). Pass A: per-head denominators. Pass B: recompute
// exp, weighted float4 gather of feat[src] in registers.
// ---------------------------------------------------------------------------
__device__ __forceinline__ float4 wred_sum4(float4 v) {
#pragma unroll
    for (int o = 16; o; o >>= 1) {
        v.x += __shfl_xor_sync(FULL, v.x, o);
        v.y += __shfl_xor_sync(FULL, v.y, o);
        v.z += __shfl_xor_sync(FULL, v.z, o);
        v.w += __shfl_xor_sync(FULL, v.w, o);
    }
    return v;
}

__global__ void k_gather(const float* __restrict__ bias, float* __restrict__ out,
                         float act_slope, int apply_act) {
    int wg = (blockIdx.x * blockDim.x + threadIdx.x) >> 5;
    int lane = threadIdx.x & 31;
    if (wg >= NN) return;
    int v = wg;
    int start = g_off[v];
    int end = start + g_counts[v];

    const float4* feat4 = reinterpret_cast<const float4*>(g_feat);
    const float4* el4 = reinterpret_cast<const float4*>(g_el);
    const float* elf = g_el;

    float4 erv = reinterpret_cast<const float4*>(g_er)[v];

    float4 sm = make_float4(0.f, 0.f, 0.f, 0.f);
    for (int p = start + lane; p < end; p += 32) {
        int s = g_ssrc[p];
        float4 e = el4[s];
        sm.x += __expf(lk(e.x + erv.x, 0.2f));
        sm.y += __expf(lk(e.y + erv.y, 0.2f));
        sm.z += __expf(lk(e.z + erv.z, 0.2f));
        sm.w += __expf(lk(e.w + erv.w, 0.2f));
    }
    sm = wred_sum4(sm);

    int h = lane >> 3;
    float shd = (h == 0) ? sm.x : (h == 1) ? sm.y : (h == 2) ? sm.z : sm.w;
    float erh = (h == 0) ? erv.x : (h == 1) ? erv.y : (h == 2) ? erv.z : erv.w;
    float inv = 1.f / shd;

    float4 a0 = make_float4(0, 0, 0, 0), a1 = a0, a2 = a0, a3 = a0;
    int p = start;
#define STEP(PP, ACC)                                            \
    {                                                            \
        int s_ = g_ssrc[PP];                                     \
        float a_ = __expf(lk(elf[s_ * 4 + h] + erh, 0.2f)) * inv;\
        float4 f_ = feat4[s_ * 32 + lane];                       \
        ACC.x = fmaf(a_, f_.x, ACC.x);                           \
        ACC.y = fmaf(a_, f_.y, ACC.y);                           \
        ACC.z = fmaf(a_, f_.z, ACC.z);                           \
        ACC.w = fmaf(a_, f_.w, ACC.w);                           \
    }
    for (; p + 4 <= end; p += 4) {
        STEP(p + 0, a0); STEP(p + 1, a1); STEP(p + 2, a2); STEP(p + 3, a3);
    }
    for (; p < end; ++p) STEP(p, a0);
#undef STEP
    float4 acc;
    acc.x = (a0.x + a1.x) + (a2.x + a3.x);
    acc.y = (a0.y + a1.y) + (a2.y + a3.y);
    acc.z = (a0.z + a1.z) + (a2.z + a3.z);
    acc.w = (a0.w + a1.w) + (a2.w + a3.w);

    float4 b = reinterpret_cast<const float4*>(bias)[lane];
    acc.x += b.x; acc.y += b.y; acc.z += b.z; acc.w += b.w;
    if (apply_act) {
        acc.x = lk(acc.x, act_slope);
        acc.y = lk(acc.y, act_slope);
        acc.z = lk(acc.z, act_slope);
        acc.w = lk(acc.w, act_slope);
    }
    reinterpret_cast<float4*>(out)[v * 32 + lane] = acc;
}

// ---------------------------------------------------------------------------
extern "C" void kernel_launch(void* const* d_in, const int* in_sizes, int n_in,
                              void* d_out, int out_size) {
    const float* x   = (const float*)d_in[0];
    const int*   src = (const int*)d_in[1];
    const int*   dst = (const int*)d_in[2];
    const float* W1  = (const float*)d_in[3];
    const float* al1 = (const float*)d_in[4];
    const float* ar1 = (const float*)d_in[5];
    const float* b1  = (const float*)d_in[6];
    const float* W2  = (const float*)d_in[7];
    const float* al2 = (const float*)d_in[8];
    const float* ar2 = (const float*)d_in[9];
    const float* b2  = (const float*)d_in[10];
    float* out = (float*)d_out;

    void* p_hid = nullptr;
    cudaGetSymbolAddress(&p_hid, g_hid);
    float* hid = (float*)p_hid;

    // dynamic smem: W 64KB + X double-buffer 2*32*130*4
    const int GEMM_SMEM = (128 * 128 + 2 * 32 * 130) * (int)sizeof(float);
    cudaFuncSetAttribute(k_gemm, cudaFuncAttributeMaxDynamicSharedMemorySize,
                         GEMM_SMEM);

    int eblocks = (EE + 255) / 256;
    int nblocks = (NN + 255) / 256;
    int gemm_blocks = (NN + 127) / 128;      // 391
    int gather_blocks = (NN + 7) / 8;        // 8 warps/block
    int off_blocks = (NN + 1023) / 1024;     // 49

    k_init<<<nblocks, 256>>>();                                // 1
    k_hist<<<eblocks, 256>>>(dst);                             // 2
    k_offsets<<<off_blocks, 1024>>>();                         // 3
    k_gemm<<<gemm_blocks, 256, GEMM_SMEM>>>(x, W1, al1, ar1);  // 4 <- ncu capture
    k_scatter<<<eblocks, 256>>>(src, dst);                     // 5
    k_gather<<<gather_blocks, 256>>>(b1, hid, 0.01f, 1);       // 6
    k_gemm<<<gemm_blocks, 256, GEMM_SMEM>>>(hid, W2, al2, ar2);// 7
    k_gather<<<gather_blocks, 256>>>(b2, out, 0.0f, 0);        // 8
}